// round 15
// baseline (speedup 1.0000x reference)
#include <cuda_runtime.h>
#include <cstdint>
#include <cstring>
#include <vector>
#include <algorithm>

// ---------------------------------------------------------------------------
// CLOPLayer: out[b,c,i] = x[b,c,idx[i]], idx fixed (JAX threefry seed 42 +
// sequential neighbor-swap scan), recomputed bit-exact on the HOST each call.
//
// R15: BAND-RESIDENT persistent blocks. Grid (PB, NBANDS): each block owns
// one band and loops over ~NPLANES/PB planes with a double-buffered
// cp.async.bulk window pipeline (R14). The band's uint16 idx slice is loaded
// into registers ONCE per block and reused across all planes — removing
// ~38MB of redundant idx L2 traffic and the per-iteration idx load chain.
// BAND=16, Lc=24 (D<=4): smem 2*24*896=43KB -> 4 blocks/SM, 64 warps/SM.
// Fused ATS idx delivery (GB300 C2C) unchanged. Replay-deterministic.
// ---------------------------------------------------------------------------

#define GH 224
#define GW 224
#define HW (GH * GW)            // 50176
#define HW4 (HW / 4)
#define NPLANES 384             // 128 * 3
#define BAND 16
#define NBANDS (GH / BAND)      // 14
#define BANDW (BAND * GW)       // 3584
#define BANDW4 (BANDW / 4)      // 896
#define NT 512
#define GITER 2                 // 896 = 512 + 384
#define HW16 (HW / 8)
#define NCOPY 16
#define CHUNK16 (HW16 / NCOPY)  // 392

__device__ unsigned short g_idxl[HW];
__device__ unsigned int g_flag[NCOPY];
__device__ int g_idx[HW];       // absolute idx (degenerate fallback)

static __device__ __forceinline__ uint32_t smem_u32(const void* p) {
    uint32_t a;
    asm("{ .reg .u64 t; cvta.to.shared.u64 t, %1; cvt.u32.u64 %0, t; }"
        : "=r"(a) : "l"(p));
    return a;
}
static __device__ __forceinline__ void mbar_init(uint32_t mb, uint32_t cnt) {
    asm volatile("mbarrier.init.shared.b64 [%0], %1;" :: "r"(mb), "r"(cnt)
                 : "memory");
}
static __device__ __forceinline__ void mbar_expect_tx(uint32_t mb, uint32_t tx) {
    asm volatile("mbarrier.arrive.expect_tx.shared.b64 _, [%0], %1;"
                 :: "r"(mb), "r"(tx) : "memory");
}
static __device__ __forceinline__ void bulk_g2s(uint32_t dst, const void* src,
                                                uint32_t bytes, uint32_t mb) {
    asm volatile(
        "cp.async.bulk.shared::cluster.global.mbarrier::complete_tx::bytes "
        "[%0], [%1], %2, [%3];"
        :: "r"(dst), "l"(src), "r"(bytes), "r"(mb) : "memory");
}
static __device__ __forceinline__ void mbar_wait(uint32_t mb, uint32_t phase) {
    asm volatile(
        "{\n\t"
        ".reg .pred P;\n\t"
        "WAIT_%=: \n\t"
        "mbarrier.try_wait.parity.acquire.cta.shared::cta.b64 P, [%0], %1, 0x989680;\n\t"
        "@P bra.uni DONE_%=;\n\t"
        "bra.uni WAIT_%=;\n\t"
        "DONE_%=: \n\t"
        "}"
        :: "r"(mb), "r"(phase) : "memory");
}
static __device__ __forceinline__ unsigned int ld_acquire(unsigned int* p) {
    unsigned int v;
    asm volatile("ld.global.acquire.gpu.u32 %0, [%1];" : "=r"(v) : "l"(p)
                 : "memory");
    return v;
}

// ---- band-resident persistent double-buffered gather ------------------------
template <int Lc>
__global__ __launch_bounds__(NT, 4)
void clop_pers(const float* __restrict__ x, float* __restrict__ out,
               const uint4* __restrict__ hidx, int do_copy) {
    extern __shared__ float sp[];                 // 2 * Lc*GW floats
    __shared__ __align__(8) unsigned long long mbar_s[2];
    constexpr uint32_t WBYTES = (uint32_t)Lc * GW * sizeof(float);

    const int band = blockIdx.y;                  // this block's band, fixed
    int ws = band * BAND - ((Lc - BAND) >> 1);    // window start row, fixed
    if (ws < 0) ws += GH;
    const int n1 = (GH - ws < Lc) ? (GH - ws) : Lc;   // rows before wrap
    const uint32_t b1 = (uint32_t)n1 * GW * sizeof(float);

    const uint32_t mb0 = smem_u32(&mbar_s[0]);
    if (threadIdx.x == 0) { mbar_init(mb0, 1); mbar_init(mb0 + 8, 1); }
    __syncthreads();

    const uint32_t sbase = smem_u32(sp);

    auto stage = [&](int plane, int buf) {
        const float* src = x + (size_t)plane * HW;
        const uint32_t mb = mb0 + 8 * buf;
        mbar_expect_tx(mb, WBYTES);
        const uint32_t sdst = sbase + (uint32_t)buf * WBYTES;
        bulk_g2s(sdst, src + (size_t)ws * GW, b1, mb);
        if (n1 < Lc) bulk_g2s(sdst + b1, src, WBYTES - b1, mb);
    };

    // prologue: first plane's DMA (independent of idx)
    const int p0 = blockIdx.x;
    if (threadIdx.x == 0 && p0 < NPLANES) stage(p0, 0);

    // fused idx delivery (ATS): copiers write chunks, everyone spins once
    if (do_copy) {
        const int bid = blockIdx.y * gridDim.x + blockIdx.x;
        if (bid < NCOPY) {
            const int base16 = bid * CHUNK16;
            if (threadIdx.x < CHUNK16) {
                reinterpret_cast<uint4*>(g_idxl)[base16 + threadIdx.x] =
                    __ldg(&hidx[base16 + threadIdx.x]);
            }
            __syncthreads();
            if (threadIdx.x == 0) {
                __threadfence();
                atomicExch(&g_flag[bid], 1u);
            }
        }
        if (threadIdx.x < NCOPY) {
            while (ld_acquire(&g_flag[threadIdx.x]) == 0u) __nanosleep(64);
        }
        __syncthreads();
    }

    // load this band's idx slice ONCE; reused for every plane
    const size_t base = (size_t)band * BANDW;
    const ushort4* id4 = reinterpret_cast<const ushort4*>(g_idxl + base);
    ushort4 idbuf[GITER];
#pragma unroll
    for (int u = 0; u < GITER; u++) {
        const int k = threadIdx.x + u * NT;
        if (k < BANDW4) idbuf[u] = __ldg(&id4[k]);
    }

    // steady-state plane loop
    int i = 0;
    for (int p = p0; p < NPLANES; p += gridDim.x, i++) {
        const int b = i & 1;
        if (threadIdx.x == 0 && p + (int)gridDim.x < NPLANES) {
            stage(p + gridDim.x, b ^ 1);   // buffer freed by prev-iter sync
        }

        mbar_wait(mb0 + 8 * b, (i >> 1) & 1);

        const float* w = sp + (size_t)b * (WBYTES / sizeof(float));
        float4* dst = reinterpret_cast<float4*>(out + (size_t)p * HW + base);
#pragma unroll
        for (int u = 0; u < GITER; u++) {
            const int k = threadIdx.x + u * NT;
            if (k < BANDW4) {
                const ushort4 id = idbuf[u];
                float4 v;
                v.x = w[id.x];
                v.y = w[id.y];
                v.z = w[id.z];
                v.w = w[id.w];
                __stcs(&dst[k], v);
            }
        }
        __syncthreads();   // all warps done reading buf b -> reusable
    }
}

// ---- degenerate fallback: full-plane gather (R1) ----------------------------
__global__ __launch_bounds__(1024, 1)
void clop_gather(const float* __restrict__ x, float* __restrict__ out) {
    extern __shared__ float sp[];
    const size_t off = (size_t)blockIdx.x * HW;
    const float4* src = reinterpret_cast<const float4*>(x + off);
    float4* sp4 = reinterpret_cast<float4*>(sp);
    for (int k = threadIdx.x; k < HW4; k += 1024) sp4[k] = src[k];
    __syncthreads();
    float4* dst = reinterpret_cast<float4*>(out + off);
    const int4* idx4 = reinterpret_cast<const int4*>(g_idx);
    for (int k = threadIdx.x; k < HW4; k += 1024) {
        int4 id = __ldg(&idx4[k]);
        float4 v;
        v.x = sp[id.x]; v.y = sp[id.y]; v.z = sp[id.z]; v.w = sp[id.w];
        __stcs(&dst[k], v);
    }
}

// ---------------------------------------------------------------------------
// Host-side exact replication of the JAX RNG pipeline (partitionable threefry)
// ---------------------------------------------------------------------------

static inline uint32_t rotl32(uint32_t x, int d) {
    return (x << d) | (x >> (32 - d));
}

struct TFKey { uint32_t hi, lo; };

static void threefry2x32(uint32_t k0, uint32_t k1, uint32_t x0, uint32_t x1,
                         uint32_t* o0, uint32_t* o1) {
    const uint32_t ks0 = k0, ks1 = k1, ks2 = k0 ^ k1 ^ 0x1BD11BDAu;
    static const int ra[4] = {13, 15, 26, 6};
    static const int rb[4] = {17, 29, 16, 24};
    x0 += ks0; x1 += ks1;
    for (int i = 0; i < 4; i++) { x0 += x1; x1 = rotl32(x1, ra[i]); x1 ^= x0; }
    x0 += ks1; x1 += ks2 + 1u;
    for (int i = 0; i < 4; i++) { x0 += x1; x1 = rotl32(x1, rb[i]); x1 ^= x0; }
    x0 += ks2; x1 += ks0 + 2u;
    for (int i = 0; i < 4; i++) { x0 += x1; x1 = rotl32(x1, ra[i]); x1 ^= x0; }
    x0 += ks0; x1 += ks1 + 3u;
    for (int i = 0; i < 4; i++) { x0 += x1; x1 = rotl32(x1, rb[i]); x1 ^= x0; }
    x0 += ks1; x1 += ks2 + 4u;
    for (int i = 0; i < 4; i++) { x0 += x1; x1 = rotl32(x1, ra[i]); x1 ^= x0; }
    x0 += ks2; x1 += ks0 + 5u;
    *o0 = x0; *o1 = x1;
}

static inline TFKey tf_child(TFKey k, uint32_t j) {
    TFKey r; threefry2x32(k.hi, k.lo, 0u, j, &r.hi, &r.lo); return r;
}
static inline uint32_t tf_bits32(TFKey k, uint32_t i) {
    uint32_t a, b; threefry2x32(k.hi, k.lo, 0u, i, &a, &b); return a ^ b;
}

static void compute_host_idx(int* h_idx) {
    const int n = HW;
    TFKey key42 = {0u, 42u};
    TFKey k1 = tf_child(key42, 0u);
    TFKey k2 = tf_child(key42, 1u);

    std::vector<int> order(n);
    for (int i = 0; i < n; i++) order[i] = i;
    {
        TFKey cur = k1;
        std::vector<uint64_t> kv(n);
        std::vector<int> nx(n);
        for (int round = 0; round < 2; round++) {
            TFKey nkey = tf_child(cur, 0u);
            TFKey sub  = tf_child(cur, 1u);
            for (int i = 0; i < n; i++)
                kv[(size_t)i] = ((uint64_t)tf_bits32(sub, (uint32_t)i) << 32) |
                                (uint32_t)i;
            std::sort(kv.begin(), kv.end());
            for (int j = 0; j < n; j++)
                nx[(size_t)j] = order[(size_t)(uint32_t)kv[(size_t)j]];
            order.swap(nx);
            cur = nkey;
        }
    }

    float p0 = (float)(1.0 - 0.3), pq = (float)(0.3 / 4.0);
    float c[5];
    c[0] = p0;
    for (int j = 1; j < 5; j++) c[j] = c[j - 1] + pq;

    std::vector<uint8_t> rs(n);
    for (int i = 0; i < n; i++) {
        uint32_t bits = tf_bits32(k2, (uint32_t)i);
        uint32_t fb = (bits >> 9) | 0x3F800000u;
        float f; std::memcpy(&f, &fb, 4);
        f -= 1.0f;
        float r = c[4] * (1.0f - f);
        int ind = 0;
        while (ind < 5 && c[ind] < r) ind++;
        rs[(size_t)i] = (uint8_t)ind;
    }

    for (int i = 0; i < n; i++) h_idx[i] = i;
    for (int t = 0; t < n; t++) {
        const int a = order[(size_t)t];
        const int r = rs[(size_t)t];
        const int i = a / GW, j = a % GW;
        const int ii = (r == 1) ? (i + 1) % GH : (r == 2) ? (i + GH - 1) % GH : i;
        const int jj = (r == 3) ? (j + 1) % GW : (r == 4) ? (j + GW - 1) % GW : j;
        const int b = (r == 0) ? a : (ii * GW + jj);
        const int va = h_idx[a], vb = h_idx[b];
        h_idx[a] = vb; h_idx[b] = va;
    }
}

// ---------------------------------------------------------------------------

template <int Lc>
static void launch_pers(const float* x, float* out, const uint4* hidx,
                        int do_copy, int pb) {
    const int smem = 2 * Lc * GW * (int)sizeof(float);
    cudaFuncSetAttribute(clop_pers<Lc>,
                         cudaFuncAttributeMaxDynamicSharedMemorySize, smem);
    dim3 grid(pb, NBANDS);
    clop_pers<Lc><<<grid, NT, smem>>>(x, out, hidx, do_copy);
}

extern "C" void kernel_launch(void* const* d_in, const int* in_sizes, int n_in,
                              void* d_out, int out_size) {
    (void)in_sizes; (void)n_in; (void)out_size;

    static int h_idx[HW];
    alignas(16) static unsigned short h_idxl[HW];   // ATS-read by the kernel
    compute_host_idx(h_idx);

    // max toroidal row distance from each output row's band window (BAND=16)
    int D = 0;
    for (int i = 0; i < HW; i++) {
        const int r_out = i / GW;
        const int bandstart = (r_out / BAND) * BAND;
        const int r_src = h_idx[i] / GW;
        int dist = 0;
        if (r_src >= bandstart && r_src < bandstart + BAND) {
            dist = 0;
        } else {
            int dlo = (bandstart - r_src + GH) % GH;
            int dhi = (r_src - (bandstart + BAND - 1) + GH) % GH;
            dist = dlo < dhi ? dlo : dhi;
        }
        if (dist > D) D = dist;
    }

    const float* x = (const float*)d_in[0];
    float* out = (float*)d_out;

    if (D > 18) {
        // degenerate fallback: full-plane gather with absolute idx memcpy
        cudaFuncSetAttribute(clop_gather,
                             cudaFuncAttributeMaxDynamicSharedMemorySize,
                             HW * (int)sizeof(float));
        cudaMemcpyToSymbolAsync(g_idx, h_idx, sizeof(h_idx), 0,
                                cudaMemcpyHostToDevice, 0);
        clop_gather<<<NPLANES, 1024, HW * sizeof(float)>>>(x, out);
        return;
    }

    // ladder (double buffer => 2*Lc*896 B per block, 14 bands in grid.y):
    // 4 blocks/SM -> pb=42 (14*42=588); 3/SM -> pb=31 (434); 2/SM -> pb=21
    int Lc, pb;
    if (D <= 2)       { Lc = 20; pb = 42; }
    else if (D <= 4)  { Lc = 24; pb = 42; }
    else if (D <= 6)  { Lc = 28; pb = 42; }
    else if (D <= 10) { Lc = 36; pb = 31; }
    else              { Lc = 52; pb = 21; }

    // window-relative row-major indices for the padded window
    const int Dp = (Lc - BAND) / 2;
    for (int i = 0; i < HW; i++) {
        const int r_out = i / GW;
        const int ws0 = (r_out / BAND) * BAND - Dp;
        const int r_src = h_idx[i] / GW;
        const int c_src = h_idx[i] % GW;
        int t = r_src - ws0;
        t %= GH; if (t < 0) t += GH;
        h_idxl[i] = (unsigned short)(t * GW + c_src);
    }

    int ats = 0;
    cudaDeviceGetAttribute(&ats, cudaDevAttrPageableMemoryAccess, 0);
    const uint4* hidx = reinterpret_cast<const uint4*>(h_idxl);

    if (!ats) {
        cudaMemcpyToSymbolAsync(g_idxl, h_idxl, sizeof(h_idxl), 0,
                                cudaMemcpyHostToDevice, 0);
    }
    const int do_copy = ats ? 1 : 0;

    if (Lc == 20)      launch_pers<20>(x, out, hidx, do_copy, pb);
    else if (Lc == 24) launch_pers<24>(x, out, hidx, do_copy, pb);
    else if (Lc == 28) launch_pers<28>(x, out, hidx, do_copy, pb);
    else if (Lc == 36) launch_pers<36>(x, out, hidx, do_copy, pb);
    else               launch_pers<52>(x, out, hidx, do_copy, pb);
}

// round 16
// speedup vs baseline: 1.0245x; 1.0245x over previous
#include <cuda_runtime.h>
#include <cstdint>
#include <cstring>
#include <vector>
#include <algorithm>

// ---------------------------------------------------------------------------
// CLOPLayer: out[b,c,i] = x[b,c,idx[i]], idx fixed (JAX threefry seed 42 +
// sequential neighbor-swap scan), recomputed bit-exact on the HOST each call.
//
// R16: R14 (best: persistent double-buffered, BAND=16, 4 blocks/SM, 64
// warps/SM, tile-major order preserving halo locality, fused ATS idx
// delivery) + ASYMMETRIC EXACT WINDOWS: host measures the exact up/down
// displacement (Dup/Ddn) of each band's sources and sizes the smem window as
// BAND+Dup+Ddn (ladder step 2, Lc in {18..28}) instead of symmetric padding
// -> lower read amplification (1.5x -> ~1.4x). Window start = bandstart-Dup.
// ---------------------------------------------------------------------------

#define GH 224
#define GW 224
#define HW (GH * GW)            // 50176
#define HW4 (HW / 4)
#define NPLANES 384             // 128 * 3
#define BAND 16
#define NBANDS (GH / BAND)      // 14
#define BANDW (BAND * GW)       // 3584
#define BANDW4 (BANDW / 4)      // 896 = 512 + 384
#define TILES (NPLANES * NBANDS) // 5376
#define NT 512
#define HW16 (HW / 8)
#define NCOPY 16
#define CHUNK16 (HW16 / NCOPY)  // 392

__device__ unsigned short g_idxl[HW];
__device__ unsigned int g_flag[NCOPY];
__device__ int g_idx[HW];       // absolute idx (degenerate fallback)

static __device__ __forceinline__ uint32_t smem_u32(const void* p) {
    uint32_t a;
    asm("{ .reg .u64 t; cvta.to.shared.u64 t, %1; cvt.u32.u64 %0, t; }"
        : "=r"(a) : "l"(p));
    return a;
}
static __device__ __forceinline__ void mbar_init(uint32_t mb, uint32_t cnt) {
    asm volatile("mbarrier.init.shared.b64 [%0], %1;" :: "r"(mb), "r"(cnt)
                 : "memory");
}
static __device__ __forceinline__ void mbar_expect_tx(uint32_t mb, uint32_t tx) {
    asm volatile("mbarrier.arrive.expect_tx.shared.b64 _, [%0], %1;"
                 :: "r"(mb), "r"(tx) : "memory");
}
static __device__ __forceinline__ void bulk_g2s(uint32_t dst, const void* src,
                                                uint32_t bytes, uint32_t mb) {
    asm volatile(
        "cp.async.bulk.shared::cluster.global.mbarrier::complete_tx::bytes "
        "[%0], [%1], %2, [%3];"
        :: "r"(dst), "l"(src), "r"(bytes), "r"(mb) : "memory");
}
static __device__ __forceinline__ void mbar_wait(uint32_t mb, uint32_t phase) {
    asm volatile(
        "{\n\t"
        ".reg .pred P;\n\t"
        "WAIT_%=: \n\t"
        "mbarrier.try_wait.parity.acquire.cta.shared::cta.b64 P, [%0], %1, 0x989680;\n\t"
        "@P bra.uni DONE_%=;\n\t"
        "bra.uni WAIT_%=;\n\t"
        "DONE_%=: \n\t"
        "}"
        :: "r"(mb), "r"(phase) : "memory");
}
static __device__ __forceinline__ unsigned int ld_acquire(unsigned int* p) {
    unsigned int v;
    asm volatile("ld.global.acquire.gpu.u32 %0, [%1];" : "=r"(v) : "l"(p)
                 : "memory");
    return v;
}

// ---- persistent double-buffered gather; window = Lc rows starting at
// (band*BAND - dup) toroidal; dup passed at runtime (same for all bands) ----
template <int Lc>
__global__ __launch_bounds__(NT, 4)
void clop_pers(const float* __restrict__ x, float* __restrict__ out,
               const uint4* __restrict__ hidx, int do_copy, int dup) {
    extern __shared__ float sp[];                 // 2 * Lc*GW floats
    __shared__ __align__(8) unsigned long long mbar_s[2];
    constexpr uint32_t WBYTES = (uint32_t)Lc * GW * sizeof(float);

    const uint32_t mb0 = smem_u32(&mbar_s[0]);
    if (threadIdx.x == 0) { mbar_init(mb0, 1); mbar_init(mb0 + 8, 1); }
    __syncthreads();

    const uint32_t sbase = smem_u32(sp);

    auto stage = [&](int tile, int buf) {
        const int plane = tile / NBANDS;
        const int band  = tile - plane * NBANDS;
        const float* src = x + (size_t)plane * HW;
        int ws = band * BAND - dup;
        if (ws < 0) ws += GH;
        const uint32_t mb = mb0 + 8 * buf;
        mbar_expect_tx(mb, WBYTES);
        const int n1 = (GH - ws < Lc) ? (GH - ws) : Lc;
        const uint32_t b1 = (uint32_t)n1 * GW * sizeof(float);
        const uint32_t sdst = sbase + (uint32_t)buf * WBYTES;
        bulk_g2s(sdst, src + (size_t)ws * GW, b1, mb);
        if (n1 < Lc) bulk_g2s(sdst + b1, src, WBYTES - b1, mb);
    };

    // prologue: first tile's DMA
    const int t0 = blockIdx.x;
    if (threadIdx.x == 0 && t0 < TILES) stage(t0, 0);

    // fused idx delivery (ATS): copiers write chunks, everyone spins once
    if (do_copy) {
        if (blockIdx.x < NCOPY) {
            const int base16 = blockIdx.x * CHUNK16;
            if (threadIdx.x < CHUNK16) {
                reinterpret_cast<uint4*>(g_idxl)[base16 + threadIdx.x] =
                    __ldg(&hidx[base16 + threadIdx.x]);
            }
            __syncthreads();
            if (threadIdx.x == 0) {
                __threadfence();
                atomicExch(&g_flag[blockIdx.x], 1u);
            }
        }
        if (threadIdx.x < NCOPY) {
            while (ld_acquire(&g_flag[threadIdx.x]) == 0u) __nanosleep(64);
        }
        __syncthreads();
    }

    // steady-state tile loop (tile-major: consecutive blocks share halo in L2)
    int i = 0;
    for (int t = t0; t < TILES; t += gridDim.x, i++) {
        const int b = i & 1;
        if (threadIdx.x == 0 && t + (int)gridDim.x < TILES) {
            stage(t + gridDim.x, b ^ 1);   // buffer freed by prev-iter sync
        }

        const int plane = t / NBANDS;
        const int band  = t - plane * NBANDS;
        const size_t base = (size_t)band * BANDW;
        const ushort4* id4 = reinterpret_cast<const ushort4*>(g_idxl + base);

        // prefetch idx (L2-hot) while the DMA streams; 896 = 512 + 384
        const ushort4 id0 = __ldg(&id4[threadIdx.x]);
        ushort4 id1;
        if (threadIdx.x < BANDW4 - NT) id1 = __ldg(&id4[threadIdx.x + NT]);

        mbar_wait(mb0 + 8 * b, (i >> 1) & 1);

        const float* w = sp + (size_t)b * (WBYTES / sizeof(float));
        float4* dst = reinterpret_cast<float4*>(out + (size_t)plane * HW + base);
        {
            float4 v;
            v.x = w[id0.x]; v.y = w[id0.y]; v.z = w[id0.z]; v.w = w[id0.w];
            __stcs(&dst[threadIdx.x], v);
        }
        if (threadIdx.x < BANDW4 - NT) {
            float4 v;
            v.x = w[id1.x]; v.y = w[id1.y]; v.z = w[id1.z]; v.w = w[id1.w];
            __stcs(&dst[threadIdx.x + NT], v);
        }
        __syncthreads();   // all warps done reading buf b -> reusable
    }
}

// ---- degenerate fallback: full-plane gather (R1) ----------------------------
__global__ __launch_bounds__(1024, 1)
void clop_gather(const float* __restrict__ x, float* __restrict__ out) {
    extern __shared__ float sp[];
    const size_t off = (size_t)blockIdx.x * HW;
    const float4* src = reinterpret_cast<const float4*>(x + off);
    float4* sp4 = reinterpret_cast<float4*>(sp);
    for (int k = threadIdx.x; k < HW4; k += 1024) sp4[k] = src[k];
    __syncthreads();
    float4* dst = reinterpret_cast<float4*>(out + off);
    const int4* idx4 = reinterpret_cast<const int4*>(g_idx);
    for (int k = threadIdx.x; k < HW4; k += 1024) {
        int4 id = __ldg(&idx4[k]);
        float4 v;
        v.x = sp[id.x]; v.y = sp[id.y]; v.z = sp[id.z]; v.w = sp[id.w];
        __stcs(&dst[k], v);
    }
}

// ---------------------------------------------------------------------------
// Host-side exact replication of the JAX RNG pipeline (partitionable threefry)
// ---------------------------------------------------------------------------

static inline uint32_t rotl32(uint32_t x, int d) {
    return (x << d) | (x >> (32 - d));
}

struct TFKey { uint32_t hi, lo; };

static void threefry2x32(uint32_t k0, uint32_t k1, uint32_t x0, uint32_t x1,
                         uint32_t* o0, uint32_t* o1) {
    const uint32_t ks0 = k0, ks1 = k1, ks2 = k0 ^ k1 ^ 0x1BD11BDAu;
    static const int ra[4] = {13, 15, 26, 6};
    static const int rb[4] = {17, 29, 16, 24};
    x0 += ks0; x1 += ks1;
    for (int i = 0; i < 4; i++) { x0 += x1; x1 = rotl32(x1, ra[i]); x1 ^= x0; }
    x0 += ks1; x1 += ks2 + 1u;
    for (int i = 0; i < 4; i++) { x0 += x1; x1 = rotl32(x1, rb[i]); x1 ^= x0; }
    x0 += ks2; x1 += ks0 + 2u;
    for (int i = 0; i < 4; i++) { x0 += x1; x1 = rotl32(x1, ra[i]); x1 ^= x0; }
    x0 += ks0; x1 += ks1 + 3u;
    for (int i = 0; i < 4; i++) { x0 += x1; x1 = rotl32(x1, rb[i]); x1 ^= x0; }
    x0 += ks1; x1 += ks2 + 4u;
    for (int i = 0; i < 4; i++) { x0 += x1; x1 = rotl32(x1, ra[i]); x1 ^= x0; }
    x0 += ks2; x1 += ks0 + 5u;
    *o0 = x0; *o1 = x1;
}

static inline TFKey tf_child(TFKey k, uint32_t j) {
    TFKey r; threefry2x32(k.hi, k.lo, 0u, j, &r.hi, &r.lo); return r;
}
static inline uint32_t tf_bits32(TFKey k, uint32_t i) {
    uint32_t a, b; threefry2x32(k.hi, k.lo, 0u, i, &a, &b); return a ^ b;
}

static void compute_host_idx(int* h_idx) {
    const int n = HW;
    TFKey key42 = {0u, 42u};
    TFKey k1 = tf_child(key42, 0u);
    TFKey k2 = tf_child(key42, 1u);

    std::vector<int> order(n);
    for (int i = 0; i < n; i++) order[i] = i;
    {
        TFKey cur = k1;
        std::vector<uint64_t> kv(n);
        std::vector<int> nx(n);
        for (int round = 0; round < 2; round++) {
            TFKey nkey = tf_child(cur, 0u);
            TFKey sub  = tf_child(cur, 1u);
            for (int i = 0; i < n; i++)
                kv[(size_t)i] = ((uint64_t)tf_bits32(sub, (uint32_t)i) << 32) |
                                (uint32_t)i;
            std::sort(kv.begin(), kv.end());
            for (int j = 0; j < n; j++)
                nx[(size_t)j] = order[(size_t)(uint32_t)kv[(size_t)j]];
            order.swap(nx);
            cur = nkey;
        }
    }

    float p0 = (float)(1.0 - 0.3), pq = (float)(0.3 / 4.0);
    float c[5];
    c[0] = p0;
    for (int j = 1; j < 5; j++) c[j] = c[j - 1] + pq;

    std::vector<uint8_t> rs(n);
    for (int i = 0; i < n; i++) {
        uint32_t bits = tf_bits32(k2, (uint32_t)i);
        uint32_t fb = (bits >> 9) | 0x3F800000u;
        float f; std::memcpy(&f, &fb, 4);
        f -= 1.0f;
        float r = c[4] * (1.0f - f);
        int ind = 0;
        while (ind < 5 && c[ind] < r) ind++;
        rs[(size_t)i] = (uint8_t)ind;
    }

    for (int i = 0; i < n; i++) h_idx[i] = i;
    for (int t = 0; t < n; t++) {
        const int a = order[(size_t)t];
        const int r = rs[(size_t)t];
        const int i = a / GW, j = a % GW;
        const int ii = (r == 1) ? (i + 1) % GH : (r == 2) ? (i + GH - 1) % GH : i;
        const int jj = (r == 3) ? (j + 1) % GW : (r == 4) ? (j + GW - 1) % GW : j;
        const int b = (r == 0) ? a : (ii * GW + jj);
        const int va = h_idx[a], vb = h_idx[b];
        h_idx[a] = vb; h_idx[b] = va;
    }
}

// ---------------------------------------------------------------------------

template <int Lc>
static void launch_pers(const float* x, float* out, const uint4* hidx,
                        int do_copy, int nblk, int dup) {
    const int smem = 2 * Lc * GW * (int)sizeof(float);
    cudaFuncSetAttribute(clop_pers<Lc>,
                         cudaFuncAttributeMaxDynamicSharedMemorySize, smem);
    clop_pers<Lc><<<nblk, NT, smem>>>(x, out, hidx, do_copy, dup);
}

extern "C" void kernel_launch(void* const* d_in, const int* in_sizes, int n_in,
                              void* d_out, int out_size) {
    (void)in_sizes; (void)n_in; (void)out_size;

    static int h_idx[HW];
    alignas(16) static unsigned short h_idxl[HW];   // ATS-read by the kernel
    compute_host_idx(h_idx);

    // exact directional displacements vs each output row's band (BAND=16):
    // Dup = max rows ABOVE bandstart a source sits; Ddn = max rows BELOW band
    int Dup = 0, Ddn = 0;
    for (int i = 0; i < HW; i++) {
        const int r_out = i / GW;
        const int bandstart = (r_out / BAND) * BAND;
        const int r_src = h_idx[i] / GW;
        if (r_src >= bandstart && r_src < bandstart + BAND) continue;
        const int dlo = (bandstart - r_src + GH) % GH;              // above
        const int dhi = (r_src - (bandstart + BAND - 1) + GH) % GH; // below
        if (dlo <= dhi) { if (dlo > Dup) Dup = dlo; }
        else            { if (dhi > Ddn) Ddn = dhi; }
    }

    const float* x = (const float*)d_in[0];
    float* out = (float*)d_out;

    const int Lneed = BAND + Dup + Ddn;
    if (Lneed > 48) {
        // degenerate fallback: full-plane gather with absolute idx memcpy
        cudaFuncSetAttribute(clop_gather,
                             cudaFuncAttributeMaxDynamicSharedMemorySize,
                             HW * (int)sizeof(float));
        cudaMemcpyToSymbolAsync(g_idx, h_idx, sizeof(h_idx), 0,
                                cudaMemcpyHostToDevice, 0);
        clop_gather<<<NPLANES, 1024, HW * sizeof(float)>>>(x, out);
        return;
    }

    // ladder step 2 (double buffer = 2*Lc*896 B): Lc<=28 -> 4 blocks/SM (592),
    // Lc<=38 -> 3 blocks/SM (444), else 2 blocks/SM (296)
    int Lc = (Lneed + 1) & ~1;          // round up to even
    if (Lc < 18) Lc = 18;
    int nblk;
    if (Lc <= 28) nblk = 592;
    else if (Lc <= 38) { Lc = (Lc + 1) & ~1; nblk = 444; }
    else { Lc = 48; nblk = 296; }

    // window-relative row-major indices; window starts Dup rows above band
    for (int i = 0; i < HW; i++) {
        const int r_out = i / GW;
        const int ws0 = (r_out / BAND) * BAND - Dup;   // may be negative
        const int r_src = h_idx[i] / GW;
        const int c_src = h_idx[i] % GW;
        int t = r_src - ws0;
        t %= GH; if (t < 0) t += GH;
        h_idxl[i] = (unsigned short)(t * GW + c_src);
    }

    int ats = 0;
    cudaDeviceGetAttribute(&ats, cudaDevAttrPageableMemoryAccess, 0);
    const uint4* hidx = reinterpret_cast<const uint4*>(h_idxl);

    if (!ats) {
        cudaMemcpyToSymbolAsync(g_idxl, h_idxl, sizeof(h_idxl), 0,
                                cudaMemcpyHostToDevice, 0);
    }
    const int do_copy = ats ? 1 : 0;

    switch (Lc) {
        case 18: launch_pers<18>(x, out, hidx, do_copy, nblk, Dup); break;
        case 20: launch_pers<20>(x, out, hidx, do_copy, nblk, Dup); break;
        case 22: launch_pers<22>(x, out, hidx, do_copy, nblk, Dup); break;
        case 24: launch_pers<24>(x, out, hidx, do_copy, nblk, Dup); break;
        case 26: launch_pers<26>(x, out, hidx, do_copy, nblk, Dup); break;
        case 28: launch_pers<28>(x, out, hidx, do_copy, nblk, Dup); break;
        case 30: launch_pers<30>(x, out, hidx, do_copy, nblk, Dup); break;
        case 32: launch_pers<32>(x, out, hidx, do_copy, nblk, Dup); break;
        case 34: launch_pers<34>(x, out, hidx, do_copy, nblk, Dup); break;
        case 36: launch_pers<36>(x, out, hidx, do_copy, nblk, Dup); break;
        case 38: launch_pers<38>(x, out, hidx, do_copy, nblk, Dup); break;
        default: launch_pers<48>(x, out, hidx, do_copy, nblk, Dup); break;
    }
}